// round 16
// baseline (speedup 1.0000x reference)
#include <cuda_runtime.h>
#include <cuda_fp16.h>
#include <math.h>
#include <stdint.h>

#define B_   4
#define L_   2048
#define DIM_ 1024
#define H_   16
#define DK_  64
#define MR_  (B_*L_)    // 8192 rows
#define BH_  (B_*H_)    // 64
#define NG_  16         // groups of 128 tokens
#define GT_  128

// ---------------- scratch (static device memory; no allocations) ----------------
__device__ __half g_preh[(size_t)MR_*4096];  // fused q|k|v|gate pre-activations (fp16)
__device__ float g_S[(size_t)NG_*BH_*DK_*DK_];
__device__ __half g_qh[MR_*DIM_], g_kh[MR_*DIM_], g_vh[MR_*DIM_];
__device__ __half g_hsh[MR_*DIM_];
__device__ __half g_o2h[MR_*DIM_];
__device__ __half g_Wh[5][DIM_*DIM_];

// ------------- mma.sync GEMM: single-pass fp16, KT=64, 3-stage cp.async ----------
#define KT    64
#define OPA   16384             // 128 rows x 128 B
#define NS    (DIM_/KT)         // 16 stages

static __device__ __forceinline__ uint32_t s2u(const void* p) {
    uint32_t a;
    asm("{ .reg .u64 t; cvta.to.shared.u64 t, %1; cvt.u32.u64 %0, t; }" : "=r"(a) : "l"(p));
    return a;
}
static __device__ __forceinline__ void ldm4(uint32_t* r, uint32_t addr) {
    asm volatile("ldmatrix.sync.aligned.m8n8.x4.shared.b16 {%0,%1,%2,%3}, [%4];"
                 : "=r"(r[0]), "=r"(r[1]), "=r"(r[2]), "=r"(r[3]) : "r"(addr));
}
static __device__ __forceinline__ void mma_f16(float* c, const uint32_t* a,
                                               uint32_t b0, uint32_t b1) {
    asm volatile("mma.sync.aligned.m16n8k16.row.col.f32.f16.f16.f32 "
                 "{%0,%1,%2,%3}, {%4,%5,%6,%7}, {%8,%9}, {%0,%1,%2,%3};"
                 : "+f"(c[0]), "+f"(c[1]), "+f"(c[2]), "+f"(c[3])
                 : "r"(a[0]), "r"(a[1]), "r"(a[2]), "r"(a[3]), "r"(b0), "r"(b1));
}
static __device__ __forceinline__ void cpa16(uint32_t dst, const void* src) {
    asm volatile("cp.async.cg.shared.global [%0], [%1], 16;" :: "r"(dst), "l"(src));
}

template <int NT, typename OT>
__global__ __launch_bounds__(256, NT == 128 ? 2 : 3)
void gemm_h1(const __half* __restrict__ Ah, const __half* __restrict__ Bh,
             OT* __restrict__ C, int ldc) {
    constexpr int OPB   = NT * 128;
    constexpr int STAGE = OPA + OPB;
    constexpr int NFR   = NT / 16;
    constexpr int NFP   = NT / 32;
    extern __shared__ char smem[];
    const int tid = threadIdx.x;
    const int bm = blockIdx.y, bn = blockIdx.x;
    const uint32_t sb = s2u(smem);

    const int lane = tid & 31, wid = tid >> 5;
    const int wm0 = (wid & 3) * 32;
    const int wn0 = (wid >> 2) * (NT / 2);
    const int g = lane >> 3, lr = lane & 7;

    float acc[2][NFR][4];
#pragma unroll
    for (int mf = 0; mf < 2; mf++)
#pragma unroll
        for (int nf = 0; nf < NFR; nf++)
#pragma unroll
            for (int e = 0; e < 4; e++) acc[mf][nf][e] = 0.f;

    auto issue_chunk = [&](int k0, uint32_t buf, int p) {
        int idx = tid + 256 * p;
        int row = idx >> 3, c = idx & 7;
        cpa16(buf + row * 128 + (((c ^ (row & 7)) & 7) << 4),
              (const char*)(Ah + ((size_t)(bm * 128 + row) * DIM_ + k0 + c * 8)));
        if (p < NFP) {
            cpa16(buf + OPA + row * 128 + (((c ^ (row & 7)) & 7) << 4),
                  (const char*)(Bh + ((size_t)(bn * NT + row) * DIM_ + k0 + c * 8)));
        }
    };
    auto load_stage = [&](int s, uint32_t buf) {
#pragma unroll
        for (int p = 0; p < 4; p++) issue_chunk(s * KT, buf, p);
        asm volatile("cp.async.commit_group;" ::: "memory");
    };

    uint32_t offA[4][2], offB[4][NFP];
#pragma unroll
    for (int ks = 0; ks < 4; ks++) {
#pragma unroll
        for (int mf = 0; mf < 2; mf++) {
            int row = wm0 + mf * 16 + (g & 1) * 8 + lr;
            int ch = ks * 2 + (g >> 1);
            offA[ks][mf] = row * 128 + (((ch ^ (row & 7)) & 7) << 4);
        }
#pragma unroll
        for (int nfp = 0; nfp < NFP; nfp++) {
            int row = wn0 + nfp * 16 + (g >> 1) * 8 + lr;
            int ch = ks * 2 + (g & 1);
            offB[ks][nfp] = row * 128 + (((ch ^ (row & 7)) & 7) << 4);
        }
    }

    uint32_t buf[3] = {sb, sb + STAGE, sb + 2*STAGE};
    load_stage(0, buf[0]);
    load_stage(1, buf[1]);

    for (int s = 0; s < NS; s++) {
        if (s == NS - 1) asm volatile("cp.async.wait_group 0;" ::: "memory");
        else             asm volatile("cp.async.wait_group 1;" ::: "memory");
        __syncthreads();

        const bool do_load = (s + 2 < NS);
        const uint32_t nbuf = buf[(s + 2) % 3];
        const int nk0 = (s + 2) * KT;
        const uint32_t aB = buf[s % 3], bB = buf[s % 3] + OPA;

#pragma unroll
        for (int ks = 0; ks < 4; ks++) {
            if (do_load) issue_chunk(nk0, nbuf, ks);
            uint32_t ah[2][4];
#pragma unroll
            for (int mf = 0; mf < 2; mf++) ldm4(ah[mf], aB + offA[ks][mf]);
#pragma unroll
            for (int nfp = 0; nfp < NFP; nfp++) {
                uint32_t bh[4];
                ldm4(bh, bB + offB[ks][nfp]);
#pragma unroll
                for (int mf = 0; mf < 2; mf++) {
#pragma unroll
                    for (int sub = 0; sub < 2; sub++)
                        mma_f16(acc[mf][nfp * 2 + sub], ah[mf], bh[2*sub], bh[2*sub+1]);
                }
            }
        }
        if (do_load) asm volatile("cp.async.commit_group;" ::: "memory");
    }

#pragma unroll
    for (int mf = 0; mf < 2; mf++) {
#pragma unroll
        for (int nf = 0; nf < NFR; nf++) {
            int row = bm * 128 + wm0 + mf * 16 + (lane >> 2);
            int col = bn * NT + wn0 + nf * 8 + (lane & 3) * 2;
            OT* p = C + (size_t)row * ldc + col;
            if constexpr (sizeof(OT) == 4) {
                *(float2*)p              = make_float2(acc[mf][nf][0], acc[mf][nf][1]);
                *(float2*)(p + 8 * ldc)  = make_float2(acc[mf][nf][2], acc[mf][nf][3]);
            } else {
                *(__half2*)p             = __halves2half2(__float2half_rn(acc[mf][nf][0]),
                                                          __float2half_rn(acc[mf][nf][1]));
                *(__half2*)(p + 8 * ldc) = __halves2half2(__float2half_rn(acc[mf][nf][2]),
                                                          __float2half_rn(acc[mf][nf][3]));
            }
        }
    }
}

// --------- single-launch fp32->fp16 rounding: 8 hs sections + 5 weights ----------
__global__ __launch_bounds__(256) void round_all(const float* __restrict__ hs,
                                                 const float* W0, const float* W1,
                                                 const float* W2, const float* W3,
                                                 const float* W4) {
    const int sec = blockIdx.y;
    int i = blockIdx.x * 256 + threadIdx.x;
    const float* src;
    __half* dst;
    if (sec < 8) {
        src = hs + (size_t)sec * 1048576;
        dst = g_hsh + (size_t)sec * 1048576;
    } else {
        const float* Ws[5] = {W0, W1, W2, W3, W4};
        src = Ws[sec - 8];
        dst = g_Wh[sec - 8];
    }
    float4 x = ((const float4*)src)[i];
    ((__half2*)dst)[2*i]     = __halves2half2(__float2half_rn(x.x), __float2half_rn(x.y));
    ((__half2*)dst)[2*i + 1] = __halves2half2(__float2half_rn(x.z), __float2half_rn(x.w));
}

// --------- conv(K=4)+residual+SiLU on fp16 pre; 8-step batched loads -------------
#define TSTRIP 32
__global__ __launch_bounds__(256) void conv3(const float* __restrict__ cq,
                                             const float* __restrict__ ck,
                                             const float* __restrict__ cv) {
    const int which = blockIdx.y;
    const float* w = (which == 0) ? cq : (which == 1) ? ck : cv;
    __half* Yh = (which == 0) ? g_qh : (which == 1) ? g_kh : g_vh;
    const int strip = blockIdx.x;
    const int b = strip / (L_ / TSTRIP);
    const int s0 = (strip % (L_ / TSTRIP)) * TSTRIP;
    const int c0 = threadIdx.x * 4;

    float wreg[4][4];
#pragma unroll
    for (int j = 0; j < 4; j++)
        *(float4*)wreg[j] = *(const float4*)(w + (size_t)(c0 + j) * 4);

    const __half* base = g_preh + ((size_t)(b * L_ + s0) * 4096) + which * 1024 + c0;
    size_t orow0 = (size_t)(b * L_ + s0) * DIM_ + c0;

    auto ld4h = [](const __half* p, float* o) {
        uint2 raw = *(const uint2*)p;
        __half2 a = *(__half2*)&raw.x, b2 = *(__half2*)&raw.y;
        o[0] = __low2float(a);  o[1] = __high2float(a);
        o[2] = __low2float(b2); o[3] = __high2float(b2);
    };

    float x1[4] = {0,0,0,0}, x2[4] = {0,0,0,0}, x3[4] = {0,0,0,0};
    if (s0 >= 1) ld4h(base - 4096, x1);
    if (s0 >= 2) ld4h(base - 2*4096, x2);
    if (s0 >= 3) ld4h(base - 3*4096, x3);

    for (int t0 = 0; t0 < TSTRIP; t0 += 8) {
        float xb[8][4];
#pragma unroll
        for (int u = 0; u < 8; u++)
            ld4h(base + (size_t)(t0 + u) * 4096, xb[u]);
#pragma unroll
        for (int u = 0; u < 8; u++) {
            float y[4];
#pragma unroll
            for (int j = 0; j < 4; j++) {
                float a = xb[u][j]*(1.f + wreg[j][3]) + x1[j]*wreg[j][2]
                        + x2[j]*wreg[j][1] + x3[j]*wreg[j][0];
                y[j] = a / (1.f + __expf(-a));
            }
            if (which < 2) {
                float ss = y[0]*y[0] + y[1]*y[1] + y[2]*y[2] + y[3]*y[3];
#pragma unroll
                for (int o = 1; o < 16; o <<= 1) ss += __shfl_xor_sync(0xffffffffu, ss, o);
                float r = rsqrtf(ss + 1e-12f);
                y[0]*=r; y[1]*=r; y[2]*=r; y[3]*=r;
            }
            size_t oo = orow0 + (size_t)(t0 + u) * DIM_;
            ((__half2*)(Yh + oo))[0] = __halves2half2(__float2half_rn(y[0]), __float2half_rn(y[1]));
            ((__half2*)(Yh + oo))[1] = __halves2half2(__float2half_rn(y[2]), __float2half_rn(y[3]));
#pragma unroll
            for (int j = 0; j < 4; j++) { x3[j] = x2[j]; x2[j] = x1[j]; x1[j] = xb[u][j]; }
        }
    }
}

// ------ per-GROUP outer product via tensor cores: S_g = k^T v over 128 tokens ----
// Transpose task map: lanes within a warp differ in t-pair (contiguous smem
// columns -> conflict-free stores); dg constant per warp.
__global__ __launch_bounds__(256) void group_outer() {
    __shared__ __half skT[64 * 136];
    __shared__ __half svT[64 * 136];
    const int gidx = blockIdx.x >> 6, bh = blockIdx.x & 63;
    const int bi = bh >> 4, hh = bh & 15;
    const int tid = threadIdx.x;
    const int lane = tid & 31, wid = tid >> 5;
    const int g = lane >> 3, lr = lane & 7;
    const int base_row = bi * L_ + gidx * GT_;
    const uint32_t sk = s2u(skT), sv = s2u(svT);

#pragma unroll
    for (int i = 0; i < 2; i++) {
        int task = tid + 256 * i;          // 0..511
        int tp = task & 63;                // t-pair 0..63 (contiguous within warp)
        int dg = task >> 6;                // 0..7 (constant within warp)
        int t0 = tp * 2;
        const __half* pk = g_kh + (size_t)(base_row + t0) * DIM_ + hh*DK_ + dg*8;
        const __half* pv = g_vh + (size_t)(base_row + t0) * DIM_ + hh*DK_ + dg*8;
        uint4 ka = *(const uint4*)pk;
        uint4 kb = *(const uint4*)(pk + DIM_);
        uint4 va = *(const uint4*)pv;
        uint4 vb = *(const uint4*)(pv + DIM_);
        const __half* kah = (const __half*)&ka;
        const __half* kbh = (const __half*)&kb;
        const __half* vah = (const __half*)&va;
        const __half* vbh = (const __half*)&vb;
#pragma unroll
        for (int j = 0; j < 8; j++) {
            *(__half2*)&skT[(dg*8 + j)*136 + t0] = __halves2half2(kah[j], kbh[j]);
            *(__half2*)&svT[(dg*8 + j)*136 + t0] = __halves2half2(vah[j], vbh[j]);
        }
    }
    __syncthreads();

    const int wm = (wid & 3) * 16;
    const int wn = (wid >> 2) * 32;
    float acc[4][4];
#pragma unroll
    for (int nf = 0; nf < 4; nf++)
#pragma unroll
        for (int e = 0; e < 4; e++) acc[nf][e] = 0.f;

#pragma unroll
    for (int ks = 0; ks < 8; ks++) {
        uint32_t a[4];
        {
            int row = wm + (g & 1)*8 + lr;
            ldm4(a, sk + row*272 + (ks*2 + (g >> 1))*16);
        }
#pragma unroll
        for (int nfp = 0; nfp < 2; nfp++) {
            int row = wn + nfp*16 + (g >> 1)*8 + lr;
            uint32_t b[4];
            ldm4(b, sv + row*272 + (ks*2 + (g & 1))*16);
#pragma unroll
            for (int sub = 0; sub < 2; sub++)
                mma_f16(acc[nfp*2 + sub], a, b[2*sub], b[2*sub+1]);
        }
    }

    float* Sg = g_S + ((size_t)gidx*BH_ + bh) * 4096;
#pragma unroll
    for (int nf = 0; nf < 4; nf++) {
        int r = wm + (lane >> 2);
        int c = wn + nf*8 + (lane & 3)*2;
        *(float2*)(Sg + r*64 + c)       = make_float2(acc[nf][0], acc[nf][1]);
        *(float2*)(Sg + (r+8)*64 + c)   = make_float2(acc[nf][2], acc[nf][3]);
    }
}

// ------------- exclusive prefix over 16 groups -----------------------------------
__global__ __launch_bounds__(256) void prefix16(const float* __restrict__ Winit) {
    int idx = blockIdx.x * 256 + threadIdx.x;
    int bh = idx >> 12;
    int e = idx & 4095;
    int hh = bh & 15;
    float acc = Winit[(size_t)hh * 4096 + e];
    float* p = g_S + (size_t)bh * 4096 + e;
#pragma unroll
    for (int c = 0; c < NG_; c++) {
        float s = *p;
        *p = acc;
        acc += s;
        p += (size_t)BH_ * 4096;
    }
}

// ------- tensor-core group attention: o = mask(q k^T) v + q W_g, + LN + gate -----
#define ASQ   0
#define ASK   18432
#define ASVT  36864
#define ASP   54272
#define ASWH  89088
#define ASWL  98304
#define ASMEM 107520

__global__ __launch_bounds__(256, 2)
void attn_grp(const float* __restrict__ gamma, const float* __restrict__ beta) {
    extern __shared__ char smem[];
    const uint32_t sb = s2u(smem);
    const int gidx = blockIdx.x >> 6, bh = blockIdx.x & 63;
    const int bi = bh >> 4, hh = bh & 15;
    const int tid = threadIdx.x;
    const int lane = tid & 31, wid = tid >> 5;
    const int g = lane >> 3, lr = lane & 7;
    const int base_row = bi * L_ + gidx * GT_;

#pragma unroll
    for (int i = 0; i < 4; i++) {
        int idx = tid + 256 * i;
        int row = idx >> 3, c = idx & 7;
        const char* sq = (const char*)(g_qh + (size_t)(base_row + row) * DIM_ + hh*DK_ + c*8);
        const char* sk = (const char*)(g_kh + (size_t)(base_row + row) * DIM_ + hh*DK_ + c*8);
        cpa16(sb + ASQ + row*144 + c*16, sq);
        cpa16(sb + ASK + row*144 + c*16, sk);
    }
    asm volatile("cp.async.commit_group;" ::: "memory");

    // vT staging with conflict-free task map (lanes differ in t-pair)
#pragma unroll
    for (int i = 0; i < 2; i++) {
        int task = tid + 256 * i;
        int tp = task & 63;
        int dg = task >> 6;
        int t0 = tp * 2;
        const __half* p0 = g_vh + (size_t)(base_row + t0) * DIM_ + hh*DK_ + dg*8;
        uint4 a = *(const uint4*)p0;
        uint4 b = *(const uint4*)(p0 + DIM_);
        const __half* ah = (const __half*)&a;
        const __half* bhp = (const __half*)&b;
#pragma unroll
        for (int j = 0; j < 8; j++)
            *(__half2*)(smem + ASVT + (dg*8 + j)*272 + t0*2) = __halves2half2(ah[j], bhp[j]);
    }

    {
        const float* Wg = g_S + ((size_t)gidx*BH_ + bh) * 4096;
#pragma unroll
        for (int it = 0; it < 4; it++) {
            int kk = (tid >> 4) + it * 16;
            int vv0 = (tid & 15) * 4;
            float4 w = *(const float4*)(Wg + kk*64 + vv0);
            float wv[4] = {w.x, w.y, w.z, w.w};
#pragma unroll
            for (int j = 0; j < 4; j++) {
                __half hi = __float2half_rn(wv[j]);
                __half lo = __float2half_rn(wv[j] - __half2float(hi));
                *(__half*)(smem + ASWH + (vv0 + j)*144 + kk*2) = hi;
                *(__half*)(smem + ASWL + (vv0 + j)*144 + kk*2) = lo;
            }
        }
    }
    asm volatile("cp.async.wait_group 0;" ::: "memory");
    __syncthreads();

    // ---- phase 1: P = q @ k^T ----
    const int wm = (wid & 3) * 32;
    {
        const int wn = (wid >> 2) * 64;
        float accP[2][8][4];
#pragma unroll
        for (int mf = 0; mf < 2; mf++)
#pragma unroll
            for (int nf = 0; nf < 8; nf++)
#pragma unroll
                for (int e = 0; e < 4; e++) accP[mf][nf][e] = 0.f;

#pragma unroll
        for (int ks = 0; ks < 4; ks++) {
            uint32_t aq[2][4];
#pragma unroll
            for (int mf = 0; mf < 2; mf++) {
                int row = wm + mf*16 + (g & 1)*8 + lr;
                ldm4(aq[mf], sb + ASQ + row*144 + (ks*2 + (g >> 1))*16);
            }
#pragma unroll
            for (int nfp = 0; nfp < 4; nfp++) {
                int row = wn + nfp*16 + (g >> 1)*8 + lr;
                uint32_t bk[4];
                ldm4(bk, sb + ASK + row*144 + (ks*2 + (g & 1))*16);
#pragma unroll
                for (int mf = 0; mf < 2; mf++)
#pragma unroll
                    for (int sub = 0; sub < 2; sub++)
                        mma_f16(accP[mf][nfp*2 + sub], aq[mf], bk[2*sub], bk[2*sub+1]);
            }
        }
#pragma unroll
        for (int mf = 0; mf < 2; mf++) {
#pragma unroll
            for (int nf = 0; nf < 8; nf++) {
                int r = wm + mf*16 + (lane >> 2);
                int c = wn + nf*8 + (lane & 3)*2;
                float e0 = (c   <= r) ? accP[mf][nf][0] : 0.f;
                float e1 = (c+1 <= r) ? accP[mf][nf][1] : 0.f;
                float e2 = (c   <= r+8) ? accP[mf][nf][2] : 0.f;
                float e3 = (c+1 <= r+8) ? accP[mf][nf][3] : 0.f;
                *(__half2*)(smem + ASP + r*272 + c*2) =
                    __halves2half2(__float2half_rn(e0), __float2half_rn(e1));
                *(__half2*)(smem + ASP + (r+8)*272 + c*2) =
                    __halves2half2(__float2half_rn(e2), __float2half_rn(e3));
            }
        }
    }
    __syncthreads();

    // ---- phase 2: o = P @ v + q @ W ----
    const int wno = (wid >> 2) * 32;
    float accO[2][4][4];
#pragma unroll
    for (int mf = 0; mf < 2; mf++)
#pragma unroll
        for (int nf = 0; nf < 4; nf++)
#pragma unroll
            for (int e = 0; e < 4; e++) accO[mf][nf][e] = 0.f;

#pragma unroll
    for (int ks = 0; ks < 8; ks++) {
        uint32_t ap[2][4];
#pragma unroll
        for (int mf = 0; mf < 2; mf++) {
            int row = wm + mf*16 + (g & 1)*8 + lr;
            ldm4(ap[mf], sb + ASP + row*272 + (ks*2 + (g >> 1))*16);
        }
#pragma unroll
        for (int nfp = 0; nfp < 2; nfp++) {
            int row = wno + nfp*16 + (g >> 1)*8 + lr;
            uint32_t bv[4];
            ldm4(bv, sb + ASVT + row*272 + (ks*2 + (g & 1))*16);
#pragma unroll
            for (int mf = 0; mf < 2; mf++)
#pragma unroll
                for (int sub = 0; sub < 2; sub++)
                    mma_f16(accO[mf][nfp*2 + sub], ap[mf], bv[2*sub], bv[2*sub+1]);
        }
    }
#pragma unroll
    for (int ks = 0; ks < 4; ks++) {
        uint32_t aq[2][4];
#pragma unroll
        for (int mf = 0; mf < 2; mf++) {
            int row = wm + mf*16 + (g & 1)*8 + lr;
            ldm4(aq[mf], sb + ASQ + row*144 + (ks*2 + (g >> 1))*16);
        }
#pragma unroll
        for (int nfp = 0; nfp < 2; nfp++) {
            int row = wno + nfp*16 + (g >> 1)*8 + lr;
            uint32_t bwh[4], bwl[4];
            ldm4(bwh, sb + ASWH + row*144 + (ks*2 + (g & 1))*16);
            ldm4(bwl, sb + ASWL + row*144 + (ks*2 + (g & 1))*16);
#pragma unroll
            for (int mf = 0; mf < 2; mf++)
#pragma unroll
                for (int sub = 0; sub < 2; sub++) {
                    mma_f16(accO[mf][nfp*2 + sub], aq[mf], bwh[2*sub], bwh[2*sub+1]);
                    mma_f16(accO[mf][nfp*2 + sub], aq[mf], bwl[2*sub], bwl[2*sub+1]);
                }
        }
    }
    __syncthreads();

#pragma unroll
    for (int mf = 0; mf < 2; mf++) {
#pragma unroll
        for (int nf = 0; nf < 4; nf++) {
            int r = wm + mf*16 + (lane >> 2);
            int c = wno + nf*8 + (lane & 3)*2;
            *(float2*)(smem + ASP + r*272 + c*4) = make_float2(accO[mf][nf][0], accO[mf][nf][1]);
            *(float2*)(smem + ASP + (r+8)*272 + c*4) = make_float2(accO[mf][nf][2], accO[mf][nf][3]);
        }
    }
    __syncthreads();

    // ---- LN over 64-dim + gate (fp16) + fp16 round ----
    {
        const int row = tid >> 1;
        const int hc = (tid & 1) * 32;
        float x[32];
#pragma unroll
        for (int j = 0; j < 8; j++)
            *(float4*)(x + 4*j) = *(const float4*)(smem + ASP + row*272 + (hc + 4*j)*4);
        float s1 = 0.f, s2 = 0.f;
#pragma unroll
        for (int j = 0; j < 32; j++) { s1 += x[j]; s2 += x[j]*x[j]; }
        s1 += __shfl_xor_sync(0xffffffffu, s1, 1);
        s2 += __shfl_xor_sync(0xffffffffu, s2, 1);
        float mu  = s1 * (1.f/64.f);
        float var = s2 * (1.f/64.f) - mu*mu;
        float inv = rsqrtf(var + 1e-5f);
        const int orow = base_row + row;
        const __half* gp = g_preh + (size_t)orow * 4096 + 3072 + hh*DK_ + hc;
        __half* op = g_o2h + (size_t)orow * DIM_ + hh*DK_ + hc;
#pragma unroll
        for (int j = 0; j < 16; j++) {
            __half2 gh = ((const __half2*)gp)[j];
            float ga = __low2float(gh), gb = __high2float(gh);
            float y0 = ((x[2*j]   - mu)*inv*gamma[hc+2*j]   + beta[hc+2*j])   * ga;
            float y1 = ((x[2*j+1] - mu)*inv*gamma[hc+2*j+1] + beta[hc+2*j+1]) * gb;
            ((__half2*)op)[j] = __halves2half2(__float2half_rn(y0), __float2half_rn(y1));
        }
    }
}

// ---------------------------------------------------------------------------------
extern "C" void kernel_launch(void* const* d_in, const int* in_sizes, int n_in,
                              void* d_out, int out_size) {
    const float* hs  = (const float*)d_in[0];
    const float* cq  = (const float*)d_in[4];
    const float* ck  = (const float*)d_in[5];
    const float* cv  = (const float*)d_in[6];
    const float* Wi  = (const float*)d_in[7];
    const float* gam = (const float*)d_in[8];
    const float* bet = (const float*)d_in[9];

    __half *preh, *hsh, *o2h, *Wh;
    cudaGetSymbolAddress((void**)&preh, g_preh);
    cudaGetSymbolAddress((void**)&hsh,  g_hsh);
    cudaGetSymbolAddress((void**)&o2h,  g_o2h);
    cudaGetSymbolAddress((void**)&Wh,   g_Wh);

    constexpr int GS128 = 3 * (OPA + 128*128);   // 96 KB
    constexpr int GS64  = 3 * (OPA + 64*128);    // 72 KB
    cudaFuncSetAttribute((gemm_h1<128, __half>), cudaFuncAttributeMaxDynamicSharedMemorySize, GS128);
    cudaFuncSetAttribute((gemm_h1<64, float>),   cudaFuncAttributeMaxDynamicSharedMemorySize, GS64);
    cudaFuncSetAttribute(attn_grp, cudaFuncAttributeMaxDynamicSharedMemorySize, ASMEM);

    {
        dim3 gr(1024, 13);
        round_all<<<gr, 256>>>(hs, (const float*)d_in[1], (const float*)d_in[2],
                               (const float*)d_in[3], (const float*)d_in[10],
                               (const float*)d_in[11]);
    }

    dim3 gg4(4096/128, MR_/128);
    gemm_h1<128, __half><<<gg4, 256, GS128>>>(hsh, Wh, preh, 4096);

    dim3 gc(B_ * (L_ / TSTRIP), 3);
    conv3<<<gc, 256>>>(cq, ck, cv);

    group_outer<<<NG_*BH_, 256>>>();
    prefix16<<<(BH_*4096)/256, 256>>>(Wi);
    attn_grp<<<NG_*BH_, 256, ASMEM>>>(gam, bet);

    dim3 gg1(DIM_/64, MR_/128);   // (16, 64)
    gemm_h1<64, float><<<gg1, 256, GS64>>>(o2h, Wh + 4*(size_t)DIM_*DIM_, (float*)d_out, DIM_);
}

// round 17
// speedup vs baseline: 1.0360x; 1.0360x over previous
#include <cuda_runtime.h>
#include <cuda_fp16.h>
#include <math.h>
#include <stdint.h>

#define B_   4
#define L_   2048
#define DIM_ 1024
#define H_   16
#define DK_  64
#define MR_  (B_*L_)    // 8192 rows
#define BH_  (B_*H_)    // 64
#define NG_  16         // groups of 128 tokens
#define GT_  128

// ---------------- scratch (static device memory; no allocations) ----------------
__device__ __half g_preh[(size_t)MR_*4096];  // fused q|k|v|gate pre-activations (fp16)
__device__ float g_S[(size_t)NG_*BH_*DK_*DK_];
__device__ __half g_qh[MR_*DIM_], g_kh[MR_*DIM_], g_vh[MR_*DIM_];
__device__ __half g_hsh[MR_*DIM_];
__device__ __half g_o2h[MR_*DIM_];
__device__ __half g_Wh[5][DIM_*DIM_];

// ------------- mma.sync GEMM: single-pass fp16, KT=64, 3-stage cp.async ----------
#define KT    64
#define OPA   16384             // 128 rows x 128 B
#define NS    (DIM_/KT)         // 16 stages

static __device__ __forceinline__ uint32_t s2u(const void* p) {
    uint32_t a;
    asm("{ .reg .u64 t; cvta.to.shared.u64 t, %1; cvt.u32.u64 %0, t; }" : "=r"(a) : "l"(p));
    return a;
}
static __device__ __forceinline__ void ldm4(uint32_t* r, uint32_t addr) {
    asm volatile("ldmatrix.sync.aligned.m8n8.x4.shared.b16 {%0,%1,%2,%3}, [%4];"
                 : "=r"(r[0]), "=r"(r[1]), "=r"(r[2]), "=r"(r[3]) : "r"(addr));
}
static __device__ __forceinline__ void mma_f16(float* c, const uint32_t* a,
                                               uint32_t b0, uint32_t b1) {
    asm volatile("mma.sync.aligned.m16n8k16.row.col.f32.f16.f16.f32 "
                 "{%0,%1,%2,%3}, {%4,%5,%6,%7}, {%8,%9}, {%0,%1,%2,%3};"
                 : "+f"(c[0]), "+f"(c[1]), "+f"(c[2]), "+f"(c[3])
                 : "r"(a[0]), "r"(a[1]), "r"(a[2]), "r"(a[3]), "r"(b0), "r"(b1));
}
static __device__ __forceinline__ void cpa16(uint32_t dst, const void* src) {
    asm volatile("cp.async.cg.shared.global [%0], [%1], 16;" :: "r"(dst), "l"(src));
}
// swizzled addr in a 64-row x 256B transposed tile: banks = ct ^ low-bits of row
static __device__ __forceinline__ uint32_t tsw(int row, int ct) {
    return (uint32_t)(row * 256 + (((ct ^ (row & 7) ^ ((row >> 3) & 7)) & 15) << 4));
}
static __device__ __forceinline__ uint32_t prmt_(uint32_t a, uint32_t b, uint32_t sel) {
    uint32_t d;
    asm("prmt.b32 %0, %1, %2, %3;" : "=r"(d) : "r"(a), "r"(b), "r"(sel));
    return d;
}
// transpose an 8x8 half tile held as 8 uint4 rows, store into swizzled buffer
static __device__ __forceinline__ void transpose_store(const uint4* w, char* dstbase,
                                                       int dg, int tg) {
    const uint32_t* ww = (const uint32_t*)w;
#pragma unroll
    for (int j = 0; j < 8; j++) {
        uint32_t sel = (j & 1) ? 0x7632u : 0x5410u;
        int wd = j >> 1;
        uint32_t o0 = prmt_(ww[0*4+wd], ww[1*4+wd], sel);
        uint32_t o1 = prmt_(ww[2*4+wd], ww[3*4+wd], sel);
        uint32_t o2 = prmt_(ww[4*4+wd], ww[5*4+wd], sel);
        uint32_t o3 = prmt_(ww[6*4+wd], ww[7*4+wd], sel);
        *(uint4*)(dstbase + tsw(dg*8 + j, tg)) = make_uint4(o0, o1, o2, o3);
    }
}

template <int NT, typename OT>
__global__ __launch_bounds__(256, NT == 128 ? 2 : 3)
void gemm_h1(const __half* __restrict__ Ah, const __half* __restrict__ Bh,
             OT* __restrict__ C, int ldc) {
    constexpr int OPB   = NT * 128;
    constexpr int STAGE = OPA + OPB;
    constexpr int NFR   = NT / 16;
    constexpr int NFP   = NT / 32;
    extern __shared__ char smem[];
    const int tid = threadIdx.x;
    const int bm = blockIdx.y, bn = blockIdx.x;
    const uint32_t sb = s2u(smem);

    const int lane = tid & 31, wid = tid >> 5;
    const int wm0 = (wid & 3) * 32;
    const int wn0 = (wid >> 2) * (NT / 2);
    const int g = lane >> 3, lr = lane & 7;

    float acc[2][NFR][4];
#pragma unroll
    for (int mf = 0; mf < 2; mf++)
#pragma unroll
        for (int nf = 0; nf < NFR; nf++)
#pragma unroll
            for (int e = 0; e < 4; e++) acc[mf][nf][e] = 0.f;

    auto issue_chunk = [&](int k0, uint32_t buf, int p) {
        int idx = tid + 256 * p;
        int row = idx >> 3, c = idx & 7;
        cpa16(buf + row * 128 + (((c ^ (row & 7)) & 7) << 4),
              (const char*)(Ah + ((size_t)(bm * 128 + row) * DIM_ + k0 + c * 8)));
        if (p < NFP) {
            cpa16(buf + OPA + row * 128 + (((c ^ (row & 7)) & 7) << 4),
                  (const char*)(Bh + ((size_t)(bn * NT + row) * DIM_ + k0 + c * 8)));
        }
    };
    auto load_stage = [&](int s, uint32_t buf) {
#pragma unroll
        for (int p = 0; p < 4; p++) issue_chunk(s * KT, buf, p);
        asm volatile("cp.async.commit_group;" ::: "memory");
    };

    uint32_t offA[4][2], offB[4][NFP];
#pragma unroll
    for (int ks = 0; ks < 4; ks++) {
#pragma unroll
        for (int mf = 0; mf < 2; mf++) {
            int row = wm0 + mf * 16 + (g & 1) * 8 + lr;
            int ch = ks * 2 + (g >> 1);
            offA[ks][mf] = row * 128 + (((ch ^ (row & 7)) & 7) << 4);
        }
#pragma unroll
        for (int nfp = 0; nfp < NFP; nfp++) {
            int row = wn0 + nfp * 16 + (g >> 1) * 8 + lr;
            int ch = ks * 2 + (g & 1);
            offB[ks][nfp] = row * 128 + (((ch ^ (row & 7)) & 7) << 4);
        }
    }

    uint32_t buf[3] = {sb, sb + STAGE, sb + 2*STAGE};
    load_stage(0, buf[0]);
    load_stage(1, buf[1]);

    for (int s = 0; s < NS; s++) {
        if (s == NS - 1) asm volatile("cp.async.wait_group 0;" ::: "memory");
        else             asm volatile("cp.async.wait_group 1;" ::: "memory");
        __syncthreads();

        const bool do_load = (s + 2 < NS);
        const uint32_t nbuf = buf[(s + 2) % 3];
        const int nk0 = (s + 2) * KT;
        const uint32_t aB = buf[s % 3], bB = buf[s % 3] + OPA;

#pragma unroll
        for (int ks = 0; ks < 4; ks++) {
            if (do_load) issue_chunk(nk0, nbuf, ks);
            uint32_t ah[2][4];
#pragma unroll
            for (int mf = 0; mf < 2; mf++) ldm4(ah[mf], aB + offA[ks][mf]);
#pragma unroll
            for (int nfp = 0; nfp < NFP; nfp++) {
                uint32_t bh[4];
                ldm4(bh, bB + offB[ks][nfp]);
#pragma unroll
                for (int mf = 0; mf < 2; mf++) {
#pragma unroll
                    for (int sub = 0; sub < 2; sub++)
                        mma_f16(acc[mf][nfp * 2 + sub], ah[mf], bh[2*sub], bh[2*sub+1]);
                }
            }
        }
        if (do_load) asm volatile("cp.async.commit_group;" ::: "memory");
    }

#pragma unroll
    for (int mf = 0; mf < 2; mf++) {
#pragma unroll
        for (int nf = 0; nf < NFR; nf++) {
            int row = bm * 128 + wm0 + mf * 16 + (lane >> 2);
            int col = bn * NT + wn0 + nf * 8 + (lane & 3) * 2;
            OT* p = C + (size_t)row * ldc + col;
            if constexpr (sizeof(OT) == 4) {
                *(float2*)p              = make_float2(acc[mf][nf][0], acc[mf][nf][1]);
                *(float2*)(p + 8 * ldc)  = make_float2(acc[mf][nf][2], acc[mf][nf][3]);
            } else {
                *(__half2*)p             = __halves2half2(__float2half_rn(acc[mf][nf][0]),
                                                          __float2half_rn(acc[mf][nf][1]));
                *(__half2*)(p + 8 * ldc) = __halves2half2(__float2half_rn(acc[mf][nf][2]),
                                                          __float2half_rn(acc[mf][nf][3]));
            }
        }
    }
}

// --------- single-launch fp32->fp16 rounding: 8 hs sections + 5 weights ----------
__global__ __launch_bounds__(256) void round_all(const float* __restrict__ hs,
                                                 const float* W0, const float* W1,
                                                 const float* W2, const float* W3,
                                                 const float* W4) {
    const int sec = blockIdx.y;
    int i = blockIdx.x * 256 + threadIdx.x;
    const float* src;
    __half* dst;
    if (sec < 8) {
        src = hs + (size_t)sec * 1048576;
        dst = g_hsh + (size_t)sec * 1048576;
    } else {
        const float* Ws[5] = {W0, W1, W2, W3, W4};
        src = Ws[sec - 8];
        dst = g_Wh[sec - 8];
    }
    float4 x = ((const float4*)src)[i];
    ((__half2*)dst)[2*i]     = __halves2half2(__float2half_rn(x.x), __float2half_rn(x.y));
    ((__half2*)dst)[2*i + 1] = __halves2half2(__float2half_rn(x.z), __float2half_rn(x.w));
}

// --------- conv(K=4)+residual+SiLU on fp16 pre; 8-step batched loads -------------
#define TSTRIP 32
__global__ __launch_bounds__(256) void conv3(const float* __restrict__ cq,
                                             const float* __restrict__ ck,
                                             const float* __restrict__ cv) {
    const int which = blockIdx.y;
    const float* w = (which == 0) ? cq : (which == 1) ? ck : cv;
    __half* Yh = (which == 0) ? g_qh : (which == 1) ? g_kh : g_vh;
    const int strip = blockIdx.x;
    const int b = strip / (L_ / TSTRIP);
    const int s0 = (strip % (L_ / TSTRIP)) * TSTRIP;
    const int c0 = threadIdx.x * 4;

    float wreg[4][4];
#pragma unroll
    for (int j = 0; j < 4; j++)
        *(float4*)wreg[j] = *(const float4*)(w + (size_t)(c0 + j) * 4);

    const __half* base = g_preh + ((size_t)(b * L_ + s0) * 4096) + which * 1024 + c0;
    size_t orow0 = (size_t)(b * L_ + s0) * DIM_ + c0;

    auto ld4h = [](const __half* p, float* o) {
        uint2 raw = *(const uint2*)p;
        __half2 a = *(__half2*)&raw.x, b2 = *(__half2*)&raw.y;
        o[0] = __low2float(a);  o[1] = __high2float(a);
        o[2] = __low2float(b2); o[3] = __high2float(b2);
    };

    float x1[4] = {0,0,0,0}, x2[4] = {0,0,0,0}, x3[4] = {0,0,0,0};
    if (s0 >= 1) ld4h(base - 4096, x1);
    if (s0 >= 2) ld4h(base - 2*4096, x2);
    if (s0 >= 3) ld4h(base - 3*4096, x3);

    for (int t0 = 0; t0 < TSTRIP; t0 += 8) {
        float xb[8][4];
#pragma unroll
        for (int u = 0; u < 8; u++)
            ld4h(base + (size_t)(t0 + u) * 4096, xb[u]);
#pragma unroll
        for (int u = 0; u < 8; u++) {
            float y[4];
#pragma unroll
            for (int j = 0; j < 4; j++) {
                float a = xb[u][j]*(1.f + wreg[j][3]) + x1[j]*wreg[j][2]
                        + x2[j]*wreg[j][1] + x3[j]*wreg[j][0];
                y[j] = a / (1.f + __expf(-a));
            }
            if (which < 2) {
                float ss = y[0]*y[0] + y[1]*y[1] + y[2]*y[2] + y[3]*y[3];
#pragma unroll
                for (int o = 1; o < 16; o <<= 1) ss += __shfl_xor_sync(0xffffffffu, ss, o);
                float r = rsqrtf(ss + 1e-12f);
                y[0]*=r; y[1]*=r; y[2]*=r; y[3]*=r;
            }
            size_t oo = orow0 + (size_t)(t0 + u) * DIM_;
            ((__half2*)(Yh + oo))[0] = __halves2half2(__float2half_rn(y[0]), __float2half_rn(y[1]));
            ((__half2*)(Yh + oo))[1] = __halves2half2(__float2half_rn(y[2]), __float2half_rn(y[3]));
#pragma unroll
            for (int j = 0; j < 4; j++) { x3[j] = x2[j]; x2[j] = x1[j]; x1[j] = xb[u][j]; }
        }
    }
}

// ------ per-GROUP outer product via tensor cores: S_g = k^T v over 128 tokens ----
// Register-blocked 8x8 transpose + swizzled 256B-pitch tiles (conflict-free).
__global__ __launch_bounds__(256) void group_outer() {
    __shared__ __half skT[64 * 128];   // 64 kk-rows x 256 B (swizzled)
    __shared__ __half svT[64 * 128];
    const int gidx = blockIdx.x >> 6, bh = blockIdx.x & 63;
    const int bi = bh >> 4, hh = bh & 15;
    const int tid = threadIdx.x;
    const int lane = tid & 31, wid = tid >> 5;
    const int g = lane >> 3, lr = lane & 7;
    const int base_row = bi * L_ + gidx * GT_;
    const uint32_t sk = s2u(skT), sv = s2u(svT);

    {   // 256 threads = 2 matrices x 128 tasks (8x8 tile each)
        const int mtx = tid >> 7;          // 0: k, 1: v
        const int task = tid & 127;
        const int dg = task & 7, tg = task >> 3;     // kk-group, t-group
        const __half* src = (mtx ? g_vh : g_kh)
            + (size_t)(base_row + tg * 8) * DIM_ + hh*DK_ + dg*8;
        uint4 w[8];
#pragma unroll
        for (int t = 0; t < 8; t++) w[t] = *(const uint4*)(src + (size_t)t * DIM_);
        transpose_store(w, (char*)(mtx ? svT : skT), dg, tg);
    }
    __syncthreads();

    const int wm = (wid & 3) * 16;
    const int wn = (wid >> 2) * 32;
    float acc[4][4];
#pragma unroll
    for (int nf = 0; nf < 4; nf++)
#pragma unroll
        for (int e = 0; e < 4; e++) acc[nf][e] = 0.f;

#pragma unroll
    for (int ks = 0; ks < 8; ks++) {
        uint32_t a[4];
        {
            int row = wm + (g & 1)*8 + lr;
            ldm4(a, sk + tsw(row, ks*2 + (g >> 1)));
        }
#pragma unroll
        for (int nfp = 0; nfp < 2; nfp++) {
            int row = wn + nfp*16 + (g >> 1)*8 + lr;
            uint32_t b[4];
            ldm4(b, sv + tsw(row, ks*2 + (g & 1)));
#pragma unroll
            for (int sub = 0; sub < 2; sub++)
                mma_f16(acc[nfp*2 + sub], a, b[2*sub], b[2*sub+1]);
        }
    }

    float* Sg = g_S + ((size_t)gidx*BH_ + bh) * 4096;
#pragma unroll
    for (int nf = 0; nf < 4; nf++) {
        int r = wm + (lane >> 2);
        int c = wn + nf*8 + (lane & 3)*2;
        *(float2*)(Sg + r*64 + c)       = make_float2(acc[nf][0], acc[nf][1]);
        *(float2*)(Sg + (r+8)*64 + c)   = make_float2(acc[nf][2], acc[nf][3]);
    }
}

// ------------- exclusive prefix over 16 groups -----------------------------------
__global__ __launch_bounds__(256) void prefix16(const float* __restrict__ Winit) {
    int idx = blockIdx.x * 256 + threadIdx.x;
    int bh = idx >> 12;
    int e = idx & 4095;
    int hh = bh & 15;
    float acc = Winit[(size_t)hh * 4096 + e];
    float* p = g_S + (size_t)bh * 4096 + e;
#pragma unroll
    for (int c = 0; c < NG_; c++) {
        float s = *p;
        *p = acc;
        acc += s;
        p += (size_t)BH_ * 4096;
    }
}

// ------- tensor-core group attention: o = mask(q k^T) v + q W_g, + LN + gate -----
#define ASQ   0              // q 128 x 144B
#define ASK   18432          // k 128 x 144B
#define ASVT  36864          // vT 64 x 256B swizzled (16 KB)
#define ASP   53248          // P 128 x 272B fp16 (reused as fp32 O)
#define ASWH  88064          // WThi 64 x 144B
#define ASWL  97280          // WTlo 64 x 144B
#define ASMEM 106496

__global__ __launch_bounds__(256, 2)
void attn_grp(const float* __restrict__ gamma, const float* __restrict__ beta) {
    extern __shared__ char smem[];
    const uint32_t sb = s2u(smem);
    const int gidx = blockIdx.x >> 6, bh = blockIdx.x & 63;
    const int bi = bh >> 4, hh = bh & 15;
    const int tid = threadIdx.x;
    const int lane = tid & 31, wid = tid >> 5;
    const int g = lane >> 3, lr = lane & 7;
    const int base_row = bi * L_ + gidx * GT_;

#pragma unroll
    for (int i = 0; i < 4; i++) {
        int idx = tid + 256 * i;
        int row = idx >> 3, c = idx & 7;
        const char* sq = (const char*)(g_qh + (size_t)(base_row + row) * DIM_ + hh*DK_ + c*8);
        const char* sk = (const char*)(g_kh + (size_t)(base_row + row) * DIM_ + hh*DK_ + c*8);
        cpa16(sb + ASQ + row*144 + c*16, sq);
        cpa16(sb + ASK + row*144 + c*16, sk);
    }
    asm volatile("cp.async.commit_group;" ::: "memory");

    // vT staging: 128 tasks, register transpose into swizzled tile
    if (tid < 128) {
        const int dg = tid & 7, tg = tid >> 3;
        const __half* src = g_vh + (size_t)(base_row + tg * 8) * DIM_ + hh*DK_ + dg*8;
        uint4 w[8];
#pragma unroll
        for (int t = 0; t < 8; t++) w[t] = *(const uint4*)(src + (size_t)t * DIM_);
        transpose_store(w, smem + ASVT, dg, tg);
    }

    {
        const float* Wg = g_S + ((size_t)gidx*BH_ + bh) * 4096;
#pragma unroll
        for (int it = 0; it < 4; it++) {
            int kk = (tid >> 4) + it * 16;
            int vv0 = (tid & 15) * 4;
            float4 w = *(const float4*)(Wg + kk*64 + vv0);
            float wv[4] = {w.x, w.y, w.z, w.w};
#pragma unroll
            for (int j = 0; j < 4; j++) {
                __half hi = __float2half_rn(wv[j]);
                __half lo = __float2half_rn(wv[j] - __half2float(hi));
                *(__half*)(smem + ASWH + (vv0 + j)*144 + kk*2) = hi;
                *(__half*)(smem + ASWL + (vv0 + j)*144 + kk*2) = lo;
            }
        }
    }
    asm volatile("cp.async.wait_group 0;" ::: "memory");
    __syncthreads();

    // ---- phase 1: P = q @ k^T ----
    const int wm = (wid & 3) * 32;
    {
        const int wn = (wid >> 2) * 64;
        float accP[2][8][4];
#pragma unroll
        for (int mf = 0; mf < 2; mf++)
#pragma unroll
            for (int nf = 0; nf < 8; nf++)
#pragma unroll
                for (int e = 0; e < 4; e++) accP[mf][nf][e] = 0.f;

#pragma unroll
        for (int ks = 0; ks < 4; ks++) {
            uint32_t aq[2][4];
#pragma unroll
            for (int mf = 0; mf < 2; mf++) {
                int row = wm + mf*16 + (g & 1)*8 + lr;
                ldm4(aq[mf], sb + ASQ + row*144 + (ks*2 + (g >> 1))*16);
            }
#pragma unroll
            for (int nfp = 0; nfp < 4; nfp++) {
                int row = wn + nfp*16 + (g >> 1)*8 + lr;
                uint32_t bk[4];
                ldm4(bk, sb + ASK + row*144 + (ks*2 + (g & 1))*16);
#pragma unroll
                for (int mf = 0; mf < 2; mf++)
#pragma unroll
                    for (int sub = 0; sub < 2; sub++)
                        mma_f16(accP[mf][nfp*2 + sub], aq[mf], bk[2*sub], bk[2*sub+1]);
            }
        }
#pragma unroll
        for (int mf = 0; mf < 2; mf++) {
#pragma unroll
            for (int nf = 0; nf < 8; nf++) {
                int r = wm + mf*16 + (lane >> 2);
                int c = wn + nf*8 + (lane & 3)*2;
                float e0 = (c   <= r) ? accP[mf][nf][0] : 0.f;
                float e1 = (c+1 <= r) ? accP[mf][nf][1] : 0.f;
                float e2 = (c   <= r+8) ? accP[mf][nf][2] : 0.f;
                float e3 = (c+1 <= r+8) ? accP[mf][nf][3] : 0.f;
                *(__half2*)(smem + ASP + r*272 + c*2) =
                    __halves2half2(__float2half_rn(e0), __float2half_rn(e1));
                *(__half2*)(smem + ASP + (r+8)*272 + c*2) =
                    __halves2half2(__float2half_rn(e2), __float2half_rn(e3));
            }
        }
    }
    __syncthreads();

    // ---- phase 2: o = P @ v + q @ W ----
    const int wno = (wid >> 2) * 32;
    float accO[2][4][4];
#pragma unroll
    for (int mf = 0; mf < 2; mf++)
#pragma unroll
        for (int nf = 0; nf < 4; nf++)
#pragma unroll
            for (int e = 0; e < 4; e++) accO[mf][nf][e] = 0.f;

#pragma unroll
    for (int ks = 0; ks < 8; ks++) {
        uint32_t ap[2][4];
#pragma unroll
        for (int mf = 0; mf < 2; mf++) {
            int row = wm + mf*16 + (g & 1)*8 + lr;
            ldm4(ap[mf], sb + ASP + row*272 + (ks*2 + (g >> 1))*16);
        }
#pragma unroll
        for (int nfp = 0; nfp < 2; nfp++) {
            int row = wno + nfp*16 + (g >> 1)*8 + lr;
            uint32_t bv[4];
            ldm4(bv, sb + ASVT + tsw(row, ks*2 + (g & 1)));
#pragma unroll
            for (int mf = 0; mf < 2; mf++)
#pragma unroll
                for (int sub = 0; sub < 2; sub++)
                    mma_f16(accO[mf][nfp*2 + sub], ap[mf], bv[2*sub], bv[2*sub+1]);
        }
    }
#pragma unroll
    for (int ks = 0; ks < 4; ks++) {
        uint32_t aq[2][4];
#pragma unroll
        for (int mf = 0; mf < 2; mf++) {
            int row = wm + mf*16 + (g & 1)*8 + lr;
            ldm4(aq[mf], sb + ASQ + row*144 + (ks*2 + (g >> 1))*16);
        }
#pragma unroll
        for (int nfp = 0; nfp < 2; nfp++) {
            int row = wno + nfp*16 + (g >> 1)*8 + lr;
            uint32_t bwh[4], bwl[4];
            ldm4(bwh, sb + ASWH + row*144 + (ks*2 + (g & 1))*16);
            ldm4(bwl, sb + ASWL + row*144 + (ks*2 + (g & 1))*16);
#pragma unroll
            for (int mf = 0; mf < 2; mf++)
#pragma unroll
                for (int sub = 0; sub < 2; sub++) {
                    mma_f16(accO[mf][nfp*2 + sub], aq[mf], bwh[2*sub], bwh[2*sub+1]);
                    mma_f16(accO[mf][nfp*2 + sub], aq[mf], bwl[2*sub], bwl[2*sub+1]);
                }
        }
    }
    __syncthreads();

#pragma unroll
    for (int mf = 0; mf < 2; mf++) {
#pragma unroll
        for (int nf = 0; nf < 4; nf++) {
            int r = wm + mf*16 + (lane >> 2);
            int c = wno + nf*8 + (lane & 3)*2;
            *(float2*)(smem + ASP + r*272 + c*4) = make_float2(accO[mf][nf][0], accO[mf][nf][1]);
            *(float2*)(smem + ASP + (r+8)*272 + c*4) = make_float2(accO[mf][nf][2], accO[mf][nf][3]);
        }
    }
    __syncthreads();

    // ---- LN over 64-dim + gate (fp16) + fp16 round ----
    {
        const int row = tid >> 1;
        const int hc = (tid & 1) * 32;
        float x[32];
#pragma unroll
        for (int j = 0; j < 8; j++)
            *(float4*)(x + 4*j) = *(const float4*)(smem + ASP + row*272 + (hc + 4*j)*4);
        float s1 = 0.f, s2 = 0.f;
#pragma unroll
        for (int j = 0; j < 32; j++) { s1 += x[j]; s2 += x[j]*x[j]; }
        s1 += __shfl_xor_sync(0xffffffffu, s1, 1);
        s2 += __shfl_xor_sync(0xffffffffu, s2, 1);
        float mu  = s1 * (1.f/64.f);
        float var = s2 * (1.f/64.f) - mu*mu;
        float inv = rsqrtf(var + 1e-5f);
        const int orow = base_row + row;
        const __half* gp = g_preh + (size_t)orow * 4096 + 3072 + hh*DK_ + hc;
        __half* op = g_o2h + (size_t)orow * DIM_ + hh*DK_ + hc;
#pragma unroll
        for (int j = 0; j < 16; j++) {
            __half2 gh = ((const __half2*)gp)[j];
            float ga = __low2float(gh), gb = __high2float(gh);
            float y0 = ((x[2*j]   - mu)*inv*gamma[hc+2*j]   + beta[hc+2*j])   * ga;
            float y1 = ((x[2*j+1] - mu)*inv*gamma[hc+2*j+1] + beta[hc+2*j+1]) * gb;
            ((__half2*)op)[j] = __halves2half2(__float2half_rn(y0), __float2half_rn(y1));
        }
    }
}

// ---------------------------------------------------------------------------------
extern "C" void kernel_launch(void* const* d_in, const int* in_sizes, int n_in,
                              void* d_out, int out_size) {
    const float* hs  = (const float*)d_in[0];
    const float* cq  = (const float*)d_in[4];
    const float* ck  = (const float*)d_in[5];
    const float* cv  = (const float*)d_in[6];
    const float* Wi  = (const float*)d_in[7];
    const float* gam = (const float*)d_in[8];
    const float* bet = (const float*)d_in[9];

    __half *preh, *hsh, *o2h, *Wh;
    cudaGetSymbolAddress((void**)&preh, g_preh);
    cudaGetSymbolAddress((void**)&hsh,  g_hsh);
    cudaGetSymbolAddress((void**)&o2h,  g_o2h);
    cudaGetSymbolAddress((void**)&Wh,   g_Wh);

    constexpr int GS128 = 3 * (OPA + 128*128);   // 96 KB
    constexpr int GS64  = 3 * (OPA + 64*128);    // 72 KB
    cudaFuncSetAttribute((gemm_h1<128, __half>), cudaFuncAttributeMaxDynamicSharedMemorySize, GS128);
    cudaFuncSetAttribute((gemm_h1<64, float>),   cudaFuncAttributeMaxDynamicSharedMemorySize, GS64);
    cudaFuncSetAttribute(attn_grp, cudaFuncAttributeMaxDynamicSharedMemorySize, ASMEM);

    {
        dim3 gr(1024, 13);
        round_all<<<gr, 256>>>(hs, (const float*)d_in[1], (const float*)d_in[2],
                               (const float*)d_in[3], (const float*)d_in[10],
                               (const float*)d_in[11]);
    }

    dim3 gg4(4096/128, MR_/128);
    gemm_h1<128, __half><<<gg4, 256, GS128>>>(hsh, Wh, preh, 4096);

    dim3 gc(B_ * (L_ / TSTRIP), 3);
    conv3<<<gc, 256>>>(cq, ck, cv);

    group_outer<<<NG_*BH_, 256>>>();
    prefix16<<<(BH_*4096)/256, 256>>>(Wi);
    attn_grp<<<NG_*BH_, 256, ASMEM>>>(gam, bet);

    dim3 gg1(DIM_/64, MR_/128);   // (16, 64)
    gemm_h1<64, float><<<gg1, 256, GS64>>>(o2h, Wh + 4*(size_t)DIM_*DIM_, (float*)d_out, DIM_);
}